// round 17
// baseline (speedup 1.0000x reference)
#include <cuda_runtime.h>
#include <cuda_bf16.h>

// DensityLoss: out[b,y,x] = loss[b,y,x] * (fg ? 10 : 1) / (H*W*B),  1/(H*W*B)=2^-23 exact.
// fg = pixel covered by >=1 of 64 boxes (half-open [y1:y2, x1:x2)).
//
// Roofline-pinned shape (six designs all land 11.4-11.9us moving the
// compulsory 64 MB at ~5.7 TB/s). This final revision is the best-measured
// config (RPC=4, 128 threads, TMA in+out) with ALL block-level sync removed:
// each warp owns one row end-to-end — its own mbarrier (init by lane 0,
// visible via syncwarp), its own 4KB bulk load, bitmap build overlapped with
// the transfer, in-place scale, and its own 4KB bulk store. Warps never
// re-couple, so the startup ramp and store drain stay smooth.

#define B_DIM 8
#define H_DIM 1024
#define W_DIM 1024
#define N_BOX 64
#define THREADS 128
#define RPC 4                         // rows per CTA, one warp per row
#define ROW_BYTES (W_DIM * 4)         // 4096
#define GRID ((B_DIM * H_DIM) / RPC)  // 2048

__global__ __launch_bounds__(THREADS)
void density_loss_kernel(const float* __restrict__ loss,
                         const int4* __restrict__ bboxes,   // [B, N] (x1,y1,x2,y2)
                         float* __restrict__ out)
{
    __shared__ __align__(16) float4 tile[RPC][W_DIM / 4];        // 16 KB
    __shared__ unsigned bm[RPC][W_DIM / 32];                     // 512 B
    __shared__ __align__(8) unsigned long long mbar[RPC];

    const int t    = threadIdx.x;
    const int lane = t & 31;
    const int w    = t >> 5;                    // warp id == row within CTA
    const int row  = (blockIdx.x << 2) + w;     // b*H + y
    const int b    = row >> 10;
    const int y    = row & (H_DIM - 1);

    const unsigned mb = (unsigned)__cvta_generic_to_shared(&mbar[w]);

    // ---- fully warp-autonomous: lane 0 inits ITS mbarrier + issues ITS load
    if (lane == 0) {
        asm volatile("mbarrier.init.shared.b64 [%0], 1;" :: "r"(mb) : "memory");
        asm volatile("mbarrier.arrive.expect_tx.shared.b64 _, [%0], %1;"
                     :: "r"(mb), "r"(ROW_BYTES) : "memory");
        unsigned dst = (unsigned)__cvta_generic_to_shared(&tile[w][0]);
        asm volatile("cp.async.bulk.shared::cta.global.mbarrier::complete_tx::bytes "
                     "[%0], [%1], %2, [%3];"
                     :: "r"(dst), "l"(loss + ((size_t)row << 10)), "r"(ROW_BYTES), "r"(mb)
                     : "memory");
    }

    // ---- build this row's coverage bitmap (overlaps the bulk copy) ----
    bm[w][lane] = 0u;
    const int4* bb = bboxes + (b << 6);
    const int4 b0 = bb[lane];
    const int4 b1 = bb[lane + 32];
    __syncwarp();     // publishes mbarrier init + bm zeroing within the warp

    #pragma unroll
    for (int k = 0; k < 2; k++) {
        const int4 bx = k ? b1 : b0;
        const int x1 = min(max(bx.x, 0), W_DIM);
        const int y1 = min(max(bx.y, 0), H_DIM);
        const int x2 = min(max(bx.z, 0), W_DIM);
        const int y2 = min(max(bx.w, 0), H_DIM);
        if (y >= y1 && y < y2 && x1 < x2) {
            const int wA = x1 >> 5;
            const int wB = (x2 - 1) >> 5;
            const unsigned mA = 0xffffffffu << (x1 & 31);
            const unsigned mB = 0xffffffffu >> (31 - ((x2 - 1) & 31));
            if (wA == wB) {
                atomicOr(&bm[w][wA], mA & mB);
            } else {
                atomicOr(&bm[w][wA], mA);
                atomicOr(&bm[w][wB], mB);
                for (int q = wA + 1; q < wB; q++)
                    bm[w][q] = 0xffffffffu;     // same-value race: benign
            }
        }
    }
    __syncwarp();

    // ---- wait for this row's data (acquire orders the ld.shared below) ----
    asm volatile(
        "{\n\t"
        ".reg .pred P;\n\t"
        "WAIT_%=:\n\t"
        "mbarrier.try_wait.parity.acquire.cta.shared::cta.b64 P, [%0], 0, 0x989680;\n\t"
        "@P bra DONE_%=;\n\t"
        "bra WAIT_%=;\n\t"
        "DONE_%=:\n\t"
        "}"
        :: "r"(mb) : "memory");

    // ---- scale in place: LDS.128 -> weight -> STS.128 ----
    const float INV = 1.0f / 8388608.0f;   // 2^-23, exact
    const float WFG = 10.0f * INV;
    const int shift = (lane & 7) << 2;

    #pragma unroll
    for (int q = 0; q < 8; q++) {
        const float4   l4  = tile[w][(q << 5) + lane];
        const unsigned nib = bm[w][(q << 2) + (lane >> 3)] >> shift;
        float4 o;
        o.x = l4.x * ((nib & 1u) ? WFG : INV);
        o.y = l4.y * ((nib & 2u) ? WFG : INV);
        o.z = l4.z * ((nib & 4u) ? WFG : INV);
        o.w = l4.w * ((nib & 8u) ? WFG : INV);
        tile[w][(q << 5) + lane] = o;
    }

    // ---- order STS before async-proxy read, then bulk store this row ----
    asm volatile("fence.proxy.async.shared::cta;" ::: "memory");
    __syncwarp();
    if (lane == 0) {
        unsigned src = (unsigned)__cvta_generic_to_shared(&tile[w][0]);
        asm volatile("cp.async.bulk.global.shared::cta.bulk_group [%0], [%1], %2;"
                     :: "l"(out + ((size_t)row << 10)), "r"(src), "r"(ROW_BYTES)
                     : "memory");
        asm volatile("cp.async.bulk.commit_group;" ::: "memory");
        asm volatile("cp.async.bulk.wait_group 0;" ::: "memory");
    }
}

extern "C" void kernel_launch(void* const* d_in, const int* in_sizes, int n_in,
                              void* d_out, int out_size)
{
    const float* loss   = (const float*)d_in[0];
    // d_in[1] = pred_densities: unused by the reference computation.
    const int4*  bboxes = (const int4*)d_in[2];
    float*       out    = (float*)d_out;

    density_loss_kernel<<<GRID, THREADS>>>(loss, bboxes, out);
}